// round 12
// baseline (speedup 1.0000x reference)
#include <cuda_runtime.h>

#define N_NODES   50000
#define N_EDGES   800000
#define IN_DIM    64
#define HD        64       // NUM_HEADS * OUT_DIM
#define NUM_HEADS 4
#define OUT_DIM   16
#define NEG_SLOPE 0.2f

typedef unsigned long long u64;

// Scratch (allocation-free rule: __device__ globals)
__device__ __align__(16) float g_feat[N_NODES * HD];
__device__ __align__(16) float g_el[N_NODES * NUM_HEADS];
__device__ __align__(16) float g_er[N_NODES * NUM_HEADS];
__device__ int g_idx64;

__device__ __forceinline__ int ld_idx(const void* p, int i, int is64) {
    if (is64) return (int)((const long long*)p)[i];
    return ((const int*)p)[i];
}

// Packed fp32x2 helpers (sm_103a FFMA2 — only reachable via PTX)
__device__ __forceinline__ u64 pack2(float x) {
    u64 r; asm("mov.b64 %0, {%1, %1};" : "=l"(r) : "f"(x)); return r;
}
__device__ __forceinline__ void ffma2(u64& d, u64 a, u64 b) {
    asm("fma.rn.f32x2 %0, %1, %2, %0;" : "+l"(d) : "l"(a), "l"(b));
}
__device__ __forceinline__ float unpack_sum(u64 v) {
    float lo, hi; asm("mov.b64 {%0, %1}, %2;" : "=f"(lo), "=f"(hi) : "l"(v));
    return lo + hi;
}

// ---------------------------------------------------------------------------
// Register-tiled dual GEMM with packed FFMA2, fused el/er epilogue.
// (Measured neutral vs R3 scalar version; kept for the saved eler launch.
// Do not churn without an fc-specific profile.)
// ---------------------------------------------------------------------------
__global__ void __launch_bounds__(256) fc_kernel(
    const float* __restrict__ h,
    const float* __restrict__ Wfc,
    const float* __restrict__ Wres,
    const float* __restrict__ attn_l,
    const float* __restrict__ attn_r,
    const int*   __restrict__ src_raw,
    float* __restrict__ out)
{
    __shared__ float  hs[64][68];     // [node_local][k], padded: bank-free loads
    __shared__ float4 ws[64][32];     // [k][col_quad] q<16: Wfc, q>=16: Wres

    int tid  = threadIdx.x;
    int base = blockIdx.x * 64;

    // --- index-width detection (int64 LE with values < 2^31: odd words == 0)
    if (blockIdx.x == 0 && tid < 32) {
        int w = src_raw[2 * tid + 1];
        unsigned bal = __ballot_sync(0xffffffffu, w == 0);
        if (tid == 0) g_idx64 = (__popc(bal) >= 30) ? 1 : 0;
    }

    // --- stage weights (coalesced float4) ---
    const float4* Wfc4  = (const float4*)Wfc;
    const float4* Wres4 = (const float4*)Wres;
    #pragma unroll
    for (int i = tid; i < 2048; i += 256) {
        int k = i >> 5, q = i & 31;
        ws[k][q] = (q < 16) ? Wfc4[k * 16 + q] : Wres4[k * 16 + (q - 16)];
    }
    // --- stage h tile (coalesced float4 in, 4-phase STS) ---
    const float4* h4 = (const float4*)h;
    #pragma unroll
    for (int i = tid; i < 1024; i += 256) {
        int nl = i >> 4, kq = i & 15;
        int node = base + nl;
        float4 v = (node < N_NODES) ? h4[node * 16 + kq]
                                    : make_float4(0.f, 0.f, 0.f, 0.f);
        *(float4*)&hs[nl][kq * 4] = v;
    }
    __syncthreads();

    int cx = tid & 15;   // cols cx*8 .. cx*8+7
    int ny = tid >> 4;   // nodes ny*4 .. ny*4+3

    u64 acc[4][4];       // [node][col_pair], pair p = cols (8cx+2p, 8cx+2p+1)
    #pragma unroll
    for (int i = 0; i < 4; i++)
        #pragma unroll
        for (int p = 0; p < 4; p++) acc[i][p] = 0ull;

    #pragma unroll 8
    for (int k = 0; k < 64; k++) {
        ulonglong2 wa = *(const ulonglong2*)&ws[k][2 * cx];      // pairs 0,1
        ulonglong2 wb = *(const ulonglong2*)&ws[k][2 * cx + 1];  // pairs 2,3
        u64 hp[4];
        #pragma unroll
        for (int i = 0; i < 4; i++) hp[i] = pack2(hs[ny * 4 + i][k]);
        #pragma unroll
        for (int i = 0; i < 4; i++) {
            ffma2(acc[i][0], hp[i], wa.x);
            ffma2(acc[i][1], hp[i], wa.y);
            ffma2(acc[i][2], hp[i], wb.x);
            ffma2(acc[i][3], hp[i], wb.y);
        }
    }

    // --- store feat / resval (u64 pairs preserve float order) ---
    #pragma unroll
    for (int i = 0; i < 4; i++) {
        int node = base + ny * 4 + i;
        if (node >= N_NODES) break;
        float* dstp = (cx < 8) ? &g_feat[node * 64 + cx * 8]
                               : &out[node * 64 + (cx - 8) * 8];
        ulonglong2 v0 = make_ulonglong2(acc[i][0], acc[i][1]);
        ulonglong2 v1 = make_ulonglong2(acc[i][2], acc[i][3]);
        *(ulonglong2*)&dstp[0] = v0;
        *(ulonglong2*)&dstp[4] = v1;
    }

    // --- fused el/er epilogue (all lanes shuffle; predicated writes) ---
    {
        int c8 = cx & 7;
        const ulonglong2* al4 = (const ulonglong2*)attn_l;  // 4 floats per ull2
        const ulonglong2* ar4 = (const ulonglong2*)attn_r;
        ulonglong2 ala = al4[2 * c8], alb = al4[2 * c8 + 1];
        ulonglong2 ara = ar4[2 * c8], arb = ar4[2 * c8 + 1];
        int head = c8 >> 1;
        #pragma unroll
        for (int i = 0; i < 4; i++) {
            u64 dl = 0ull, dr = 0ull;
            ffma2(dl, acc[i][0], ala.x); ffma2(dl, acc[i][1], ala.y);
            ffma2(dl, acc[i][2], alb.x); ffma2(dl, acc[i][3], alb.y);
            ffma2(dr, acc[i][0], ara.x); ffma2(dr, acc[i][1], ara.y);
            ffma2(dr, acc[i][2], arb.x); ffma2(dr, acc[i][3], arb.y);
            float pl = unpack_sum(dl);
            float pr = unpack_sum(dr);
            pl += __shfl_xor_sync(0xffffffffu, pl, 1);
            pr += __shfl_xor_sync(0xffffffffu, pr, 1);
            int node = base + ny * 4 + i;
            if (cx < 8 && (cx & 1) == 0 && node < N_NODES) {
                g_el[node * 4 + head] = pl;
                g_er[node * 4 + head] = pr;
            }
        }
    }
}

// ---------------------------------------------------------------------------
// Edge scatter, 8 lanes/edge (v8 RED rejected by ptxas: f32 REDs cap at .v4 /
// 128-bit). Lane j (0..7): head = j>>1, half = j&1 -> cols head*16 + half*8.
// Softmax over heads via shfl_xor 2 (head bit0) and 4 (head bit1); groups
// aligned (8 | 32), grid has no ragged warps (6.4M = 25000 full blocks).
// Per lane: 2x LDG.128 gather + 2x red.global.add.v4.f32.
// vs R8: mem-pipe ops/edge 96 -> 64, threads 12.8M -> 6.4M; RED count equal.
// ---------------------------------------------------------------------------
__global__ void __launch_bounds__(256) scatter_kernel(
    const void* __restrict__ src,
    const void* __restrict__ dst,
    float* __restrict__ out)
{
    int t = blockIdx.x * 256 + threadIdx.x;              // 6.4M threads
    int e = t >> 3;
    if (e >= N_EDGES) return;
    int j  = t & 7;
    int hh = j >> 1;           // head
    int hf = j & 1;            // half of the 16-dim head

    int is64 = g_idx64;
    int s = ld_idx(src, e, is64);
    int d = ld_idx(dst, e, is64);

    float ev = g_el[s * 4 + hh] + g_er[d * 4 + hh];
    ev = (ev > 0.f) ? ev : NEG_SLOPE * ev;

    // max & sum across the 4 heads (xor 2 flips head bit0, xor 4 flips bit1)
    float m = ev;
    m = fmaxf(m, __shfl_xor_sync(0xffffffffu, m, 2));
    m = fmaxf(m, __shfl_xor_sync(0xffffffffu, m, 4));
    float x = __expf(ev - m);
    float ssum = x;
    ssum += __shfl_xor_sync(0xffffffffu, ssum, 2);
    ssum += __shfl_xor_sync(0xffffffffu, ssum, 4);
    float a = __fdividef(x, ssum);

    int col = hh * 16 + hf * 8;                          // 32B aligned
    const float4* fp = (const float4*)&g_feat[s * 64 + col];
    float4 f0 = fp[0];
    float4 f1 = fp[1];

    float* addr = out + (long long)d * 64 + col;
    asm volatile("red.global.add.v4.f32 [%0], {%1,%2,%3,%4};"
                 :: "l"(addr),
                    "f"(f0.x * a), "f"(f0.y * a), "f"(f0.z * a), "f"(f0.w * a)
                 : "memory");
    asm volatile("red.global.add.v4.f32 [%0], {%1,%2,%3,%4};"
                 :: "l"(addr + 4),
                    "f"(f1.x * a), "f"(f1.y * a), "f"(f1.z * a), "f"(f1.w * a)
                 : "memory");
}

// ---------------------------------------------------------------------------
extern "C" void kernel_launch(void* const* d_in, const int* in_sizes, int n_in,
                              void* d_out, int out_size) {
    const float* h    = (const float*)d_in[0];
    const void*  src  = d_in[1];
    const void*  dst  = d_in[2];
    const float* Wfc  = (const float*)d_in[3];
    const float* al   = (const float*)d_in[4];
    const float* ar   = (const float*)d_in[5];
    const float* Wres = (const float*)d_in[6];
    float* out = (float*)d_out;

    int fc_blocks = (N_NODES + 63) / 64;                 // 782
    fc_kernel<<<fc_blocks, 256>>>(h, Wfc, Wres, al, ar, (const int*)src, out);

    long long threads = (long long)N_EDGES * 8;          // 6.4M
    int sc_blocks = (int)((threads + 255) / 256);
    scatter_kernel<<<sc_blocks, 256>>>(src, dst, out);
}